// round 15
// baseline (speedup 1.0000x reference)
#include <cuda_runtime.h>
#include <cuda_fp16.h>

#define B_    8
#define SQ_   1024
#define SK_   1024
#define QDIM  2048
#define KVDIM 1024
#define EDIM  2048
#define H_    16
#define HD_   128

// Scratch (allocation-free: __device__ globals)
__device__ __half g_qh[(size_t)B_ * H_ * SQ_ * HD_];   // [B,H,SQ,HD] fp16 (scaled by HD^-0.5*log2e)
__device__ __half g_kh[(size_t)B_ * H_ * SK_ * HD_];
__device__ __half g_vh[(size_t)B_ * H_ * SK_ * HD_];
__device__ __half g_oh[(size_t)B_ * SQ_ * EDIM];       // attention out, fp16 [B,SQ,E]
__device__ __half g_x16[33554432];                     // fp16 query|key|value
__device__ __half g_w16[12582912];                     // fp16 Wq|Wk|Wv|Wo
__device__ unsigned g_mpack[(size_t)B_ * SQ_ * (SK_ / 32)];  // packed mask bits (1MB)

// ---------------------------------------------------------------------------
// PTX helpers
// ---------------------------------------------------------------------------
__device__ __forceinline__ unsigned smem_u32(const void* p) {
    return (unsigned)__cvta_generic_to_shared(p);
}
__device__ __forceinline__ void ldm_x4(unsigned* r, unsigned addr) {
    asm volatile("ldmatrix.sync.aligned.m8n8.x4.shared.b16 {%0,%1,%2,%3}, [%4];"
                 : "=r"(r[0]), "=r"(r[1]), "=r"(r[2]), "=r"(r[3]) : "r"(addr));
}
__device__ __forceinline__ void ldm_x4_t(unsigned* r, unsigned addr) {
    asm volatile("ldmatrix.sync.aligned.m8n8.x4.trans.shared.b16 {%0,%1,%2,%3}, [%4];"
                 : "=r"(r[0]), "=r"(r[1]), "=r"(r[2]), "=r"(r[3]) : "r"(addr));
}
__device__ __forceinline__ void mma16816(float* d, const unsigned* a, unsigned b0, unsigned b1) {
    asm volatile("mma.sync.aligned.m16n8k16.row.col.f32.f16.f16.f32 "
                 "{%0,%1,%2,%3}, {%4,%5,%6,%7}, {%8,%9}, {%0,%1,%2,%3};"
                 : "+f"(d[0]), "+f"(d[1]), "+f"(d[2]), "+f"(d[3])
                 : "r"(a[0]), "r"(a[1]), "r"(a[2]), "r"(a[3]), "r"(b0), "r"(b1));
}
__device__ __forceinline__ void cp16(unsigned saddr, const void* g) {
    asm volatile("cp.async.cg.shared.global [%0], [%1], 16;" :: "r"(saddr), "l"(g) : "memory");
}
__device__ __forceinline__ void cp_commit() {
    asm volatile("cp.async.commit_group;" ::: "memory");
}
template <int N>
__device__ __forceinline__ void cp_wait() {
    asm volatile("cp.async.wait_group %0;" :: "n"(N) : "memory");
}
__device__ __forceinline__ unsigned pack_h2(float a, float b) {
    __half2 h = __floats2half2_rn(a, b);
    return *reinterpret_cast<unsigned*>(&h);
}
__device__ __forceinline__ unsigned ex2_h2(unsigned x) {
    unsigned r;
    asm("ex2.approx.f16x2 %0, %1;" : "=r"(r) : "r"(x));
    return r;
}

// ---------------------------------------------------------------------------
// Fused prep: fp32->fp16 converts (32 elts/thread: 8 independent LDG.128,
// MLP=8) + mask bit-packing. Conv blocks handle 8192 elts each.
// Partition (8192-elt units): q 2048 | k 1024 | v 1024 | wq 512 | wk 256 |
// wv 256 | wo 512 => 5632 conv blocks; mask blocks [5632, 6656).
// ---------------------------------------------------------------------------
__global__ void __launch_bounds__(256)
prep_kernel(const float* __restrict__ q, const float* __restrict__ k,
            const float* __restrict__ v, const float* __restrict__ wq,
            const float* __restrict__ wk, const float* __restrict__ wv,
            const float* __restrict__ wo, const int* __restrict__ mask)
{
    int blk = blockIdx.x;
    if (blk >= 5632) {
        int warp = ((blk - 5632) << 3) + (threadIdx.x >> 5);   // row 0..8191
        int lane = threadIdx.x & 31;
        const int* rowp = mask + (size_t)warp * SK_;
        unsigned* op = g_mpack + (size_t)warp * (SK_ / 32);
#pragma unroll
        for (int w = 0; w < SK_ / 32; w++) {
            int mv = rowp[w * 32 + lane];
            unsigned word = __ballot_sync(0xffffffffu, mv != 0);
            if (lane == 0) op[w] = word;
        }
        return;
    }
    const float* src;
    __half* dst;
    int rel;
    if (blk < 2048)        { src = q;  dst = g_x16;            rel = blk; }
    else if (blk < 3072)   { src = k;  dst = g_x16 + 16777216; rel = blk - 2048; }
    else if (blk < 4096)   { src = v;  dst = g_x16 + 25165824; rel = blk - 3072; }
    else if (blk < 4608)   { src = wq; dst = g_w16;            rel = blk - 4096; }
    else if (blk < 4864)   { src = wk; dst = g_w16 + 4194304;  rel = blk - 4608; }
    else if (blk < 5120)   { src = wv; dst = g_w16 + 6291456;  rel = blk - 4864; }
    else                   { src = wo; dst = g_w16 + 8388608;  rel = blk - 5120; }

    int i = (rel * 256 + threadIdx.x) * 32;
    float4 f[8];
#pragma unroll
    for (int u = 0; u < 8; u++) f[u] = *(const float4*)(src + i + u * 4);
#pragma unroll
    for (int u = 0; u < 4; u++) {
        __half2 h[4];
        h[0] = __floats2half2_rn(f[2 * u].x, f[2 * u].y);
        h[1] = __floats2half2_rn(f[2 * u].z, f[2 * u].w);
        h[2] = __floats2half2_rn(f[2 * u + 1].x, f[2 * u + 1].y);
        h[3] = __floats2half2_rn(f[2 * u + 1].z, f[2 * u + 1].w);
        *(int4*)(dst + i + u * 8) = *(int4*)h;
    }
}

// ---------------------------------------------------------------------------
// GEMM body (round-9/11 verified config). C = A @ W^T + bias, *scale.
// 128x128 block, 256 threads, 8 warps (4Mx2N), warp 32x64, BK=64, 3-stage.
// MODE 0: fp32 row-major out (write-through, never re-read).
// MODE 1: fp16 head-split out.
// ---------------------------------------------------------------------------
#define G_LDS   72
#define G_STAGE (256 * G_LDS)

template <int MODE>
__device__ __forceinline__ void
gemm_body(const __half* __restrict__ A, const __half* __restrict__ W,
          const float* __restrict__ bias, int N, int K,
          float out_scale, float* __restrict__ outF, __half* __restrict__ outH,
          __half* smem)
{
    constexpr int BK = 64, S = 3;

    const int tid  = threadIdx.x;
    const int wid  = tid >> 5;
    const int lane = tid & 31;
    const int warpM = wid >> 1;
    const int warpN = wid & 1;
    const int bm0 = blockIdx.y * 128;
    const int bn0 = blockIdx.x * 128;
    const int T = K / BK;

    const int cp_row = tid >> 3;
    const int cp_c8  = (tid & 7) * 8;

    auto copy_tile = [&](int t, int s) {
        __half* sA = smem + s * G_STAGE;
        __half* sB = sA + 128 * G_LDS;
        const __half* ga = A + (size_t)bm0 * K + t * BK;
        const __half* gw = W + (size_t)bn0 * K + t * BK;
#pragma unroll
        for (int it = 0; it < 4; it++) {
            int row = it * 32 + cp_row;
            cp16(smem_u32(sA + row * G_LDS + cp_c8), ga + (size_t)row * K + cp_c8);
            cp16(smem_u32(sB + row * G_LDS + cp_c8), gw + (size_t)row * K + cp_c8);
        }
    };

    float acc[2][8][4];
#pragma unroll
    for (int i = 0; i < 2; i++)
#pragma unroll
        for (int j = 0; j < 8; j++)
#pragma unroll
            for (int c = 0; c < 4; c++) acc[i][j][c] = 0.0f;

    const int a_row = warpM * 32 + (lane & 15);
    const int a_co  = (lane >> 4) * 8;
    const int b_row = warpN * 64 + (lane & 15);
    const int b_co  = ((lane >> 4) & 1) * 8;

    copy_tile(0, 0); cp_commit();
    copy_tile(1, 1); cp_commit();

    for (int t = 0; t < T; t++) {
        cp_wait<S - 2>();
        __syncthreads();
        if (t + S - 1 < T) copy_tile(t + S - 1, (t + S - 1) % S);
        cp_commit();

        const __half* sA = smem + (t % S) * G_STAGE;
        const __half* sB = sA + 128 * G_LDS;
#pragma unroll
        for (int kt = 0; kt < 4; kt++) {
            unsigned a0[4], a1[4];
            ldm_x4(a0, smem_u32(sA + (a_row)      * G_LDS + kt * 16 + a_co));
            ldm_x4(a1, smem_u32(sA + (a_row + 16) * G_LDS + kt * 16 + a_co));
#pragma unroll
            for (int nj = 0; nj < 4; nj++) {
                unsigned bb[4];
                ldm_x4(bb, smem_u32(sB + (b_row + nj * 16) * G_LDS + kt * 16 + b_co));
                mma16816(acc[0][2 * nj],     a0, bb[0], bb[2]);
                mma16816(acc[0][2 * nj + 1], a0, bb[1], bb[3]);
                mma16816(acc[1][2 * nj],     a1, bb[0], bb[2]);
                mma16816(acc[1][2 * nj + 1], a1, bb[1], bb[3]);
            }
        }
    }

    const int gid = lane >> 2;
    const int tig = lane & 3;
#pragma unroll
    for (int mi = 0; mi < 2; mi++) {
        int m = bm0 + warpM * 32 + mi * 16 + gid;
#pragma unroll
        for (int nj = 0; nj < 8; nj++) {
            int n = bn0 + warpN * 64 + nj * 8 + tig * 2;
            float2 bv = *(const float2*)(bias + n);
            float v0 = (acc[mi][nj][0] + bv.x) * out_scale;
            float v1 = (acc[mi][nj][1] + bv.y) * out_scale;
            float v2 = (acc[mi][nj][2] + bv.x) * out_scale;
            float v3 = (acc[mi][nj][3] + bv.y) * out_scale;
            if (MODE == 0) {
                float2 w0 = {v0, v1}, w1 = {v2, v3};
                __stwt((float2*)(outF + (size_t)m * N + n), w0);
                __stwt((float2*)(outF + (size_t)(m + 8) * N + n), w1);
            } else {
                int b = m >> 10, s = m & 1023;
                int h = n >> 7,  d = n & 127;
                __half* p = outH + (((size_t)b * H_ + h) * SQ_ + s) * HD_ + d;
                *(__half2*)p = __floats2half2_rn(v0, v1);
                *(__half2*)(p + 8 * HD_) = __floats2half2_rn(v2, v3);
            }
        }
    }
}

// Merged Q/K/V projection launch: blockIdx.z selects the GEMM.
__global__ void __launch_bounds__(256, 2)
gemm_qkv_kernel(const float* __restrict__ bq, const float* __restrict__ bk,
                const float* __restrict__ bv)
{
    extern __shared__ __half smem[];
    const float qscale = 0.12751879526654466f;   // HD^-0.5 * log2(e)
    int z = blockIdx.z;
    if (z == 0) {
        gemm_body<1>(g_x16, g_w16, bq, EDIM, QDIM, qscale, nullptr, g_qh, smem);
    } else if (z == 1) {
        gemm_body<1>(g_x16 + 16777216, g_w16 + 4194304, bk, EDIM, KVDIM, 1.0f, nullptr, g_kh, smem);
    } else {
        gemm_body<1>(g_x16 + 25165824, g_w16 + 6291456, bv, EDIM, KVDIM, 1.0f, nullptr, g_vh, smem);
    }
}

// Output projection: C = g_oh @ Wo^T + bo -> fp32 d_out.
__global__ void __launch_bounds__(256, 2)
gemm_out_kernel(const float* __restrict__ bo, float* __restrict__ out)
{
    extern __shared__ __half smem[];
    gemm_body<0>(g_oh, g_w16 + 8388608, bo, EDIM, EDIM, 1.0f, out, nullptr, smem);
}

// ---------------------------------------------------------------------------
// Single-pass FlashAttention, fixed-shift log2-domain softmax (verified R8)
// + hoisted mask fast path (verified R14). SST=136, 2-buffer KV, 2 CTAs/SM.
// ---------------------------------------------------------------------------
#define SST 136
#define ONES_H2 0x3C003C00u

__global__ void __launch_bounds__(256, 2)
attn_kernel()
{
    extern __shared__ __half sm[];
    __half* Qs = sm;

    const int tid  = threadIdx.x;
    const int warp = tid >> 5;
    const int lane = tid & 31;
    const int gid  = lane >> 2;
    const int tig  = lane & 3;
    const int q0   = blockIdx.x * 128;
    const int bh   = blockIdx.y;
    const int b    = bh >> 4;
    const int h    = bh & 15;
    const int m0   = warp * 16;

    const __half* qbase = g_qh + ((size_t)bh * SQ_ + q0) * HD_;
#pragma unroll
    for (int it = 0; it < 8; it++) {
        int slot = it * 256 + tid;
        int r = slot >> 4, c8 = slot & 15;
        *(int4*)(Qs + r * SST + c8 * 8) = *(const int4*)(qbase + r * HD_ + c8 * 8);
    }

    const __half* kroot = g_kh + (size_t)bh * SK_ * HD_;
    const __half* vroot = g_vh + (size_t)bh * SK_ * HD_;

    auto copy_tile = [&](int j, int buf) {
        const __half* kb = kroot + (size_t)j * 64 * HD_;
        const __half* vb = vroot + (size_t)j * 64 * HD_;
        __half* ks = sm + (128 + 128 * buf) * SST;
        __half* vs = ks + 64 * SST;
#pragma unroll
        for (int it = 0; it < 4; it++) {
            int slot = it * 256 + tid;
            int r = slot >> 4, c8 = slot & 15;
            cp16(smem_u32(ks + r * SST + c8 * 8), kb + r * HD_ + c8 * 8);
            cp16(smem_u32(vs + r * SST + c8 * 8), vb + r * HD_ + c8 * 8);
        }
    };

    copy_tile(0, 0);
    cp_commit();

    // Hoisted mask check: are both of this thread's rows fully unmasked?
    const unsigned* mp0 = g_mpack + (size_t)(b * SQ_ + q0 + m0 + gid) * (SK_ / 32);
    const unsigned* mp1 = mp0 + 8 * (SK_ / 32);
    unsigned allw = ~0u;
#pragma unroll
    for (int w4 = 0; w4 < 8; w4++) {
        uint4 a = *(const uint4*)(mp0 + w4 * 4);
        uint4 c = *(const uint4*)(mp1 + w4 * 4);
        allw &= a.x & a.y & a.z & a.w & c.x & c.y & c.z & c.w;
    }
    const bool rows_unmasked = (allw == ~0u);

    float of[16][4];
#pragma unroll
    for (int i = 0; i < 16; i++)
#pragma unroll
        for (int j = 0; j < 4; j++) of[i][j] = 0.0f;
    float lacc[4] = {0.0f, 0.0f, 0.0f, 0.0f};   // ones-MMA row sums

    const unsigned q_row = m0 + (lane & 15);
    const unsigned q_coff = (lane >> 4) * 8;
    const unsigned kb_row = lane & 15;
    const unsigned kb_coff = ((lane >> 4) & 1) * 8;
    const unsigned vb_coff = (lane >> 4) * 8;

    for (int j = 0; j < 16; j++) {
        const int buf = j & 1;
        if (j < 15) {
            copy_tile(j + 1, buf ^ 1);
            cp_commit();
            cp_wait<1>();
        } else {
            cp_wait<0>();
        }
        __syncthreads();

        __half* ks = sm + (128 + 128 * buf) * SST;
        __half* vs = ks + 64 * SST;

        // ---- S = Q @ K^T (log2-domain scores) ----
        float sfr[8][4];
#pragma unroll
        for (int nt = 0; nt < 8; nt++)
#pragma unroll
            for (int c = 0; c < 4; c++) sfr[nt][c] = 0.0f;

#pragma unroll
        for (int kt = 0; kt < 8; kt++) {
            unsigned a[4];
            ldm_x4(a, smem_u32(Qs + q_row * SST + kt * 16 + q_coff));
#pragma unroll
            for (int dnt = 0; dnt < 4; dnt++) {
                unsigned bb[4];
                ldm_x4(bb, smem_u32(ks + (dnt * 16 + kb_row) * SST + kt * 16 + kb_coff));
                mma16816(sfr[2 * dnt],     a, bb[0], bb[2]);
                mma16816(sfr[2 * dnt + 1], a, bb[1], bb[3]);
            }
        }

        // ---- P = 2^S via ex2.f16x2 (hoisted fast path: no loads, no selects) ----
        unsigned ph[8][2];
        if (rows_unmasked) {
#pragma unroll
            for (int nt = 0; nt < 8; nt++) {
                ph[nt][0] = ex2_h2(pack_h2(sfr[nt][0], sfr[nt][1]));
                ph[nt][1] = ex2_h2(pack_h2(sfr[nt][2], sfr[nt][3]));
            }
        } else {
            uint2 w0 = *(const uint2*)(mp0 + j * 2);
            uint2 w1 = *(const uint2*)(mp1 + j * 2);
            unsigned long long M0 = (unsigned long long)w0.x | ((unsigned long long)w0.y << 32);
            unsigned long long M1 = (unsigned long long)w1.x | ((unsigned long long)w1.y << 32);
#pragma unroll
            for (int nt = 0; nt < 8; nt++) {
                int sh = nt * 8 + tig * 2;
                float s0 = ((M0 >> sh) & 1)       ? sfr[nt][0] : -30000.0f;
                float s1 = ((M0 >> (sh + 1)) & 1) ? sfr[nt][1] : -30000.0f;
                float s2 = ((M1 >> sh) & 1)       ? sfr[nt][2] : -30000.0f;
                float s3 = ((M1 >> (sh + 1)) & 1) ? sfr[nt][3] : -30000.0f;
                ph[nt][0] = ex2_h2(pack_h2(s0, s1));
                ph[nt][1] = ex2_h2(pack_h2(s2, s3));
            }
        }

        // ---- O += P @ V;  l += P @ ones ----
#pragma unroll
        for (int kt = 0; kt < 4; kt++) {
            unsigned a[4] = { ph[2 * kt][0], ph[2 * kt][1], ph[2 * kt + 1][0], ph[2 * kt + 1][1] };
            mma16816(lacc, a, ONES_H2, ONES_H2);
#pragma unroll
            for (int dnt = 0; dnt < 8; dnt++) {
                unsigned bb[4];
                ldm_x4_t(bb, smem_u32(vs + (kt * 16 + kb_row) * SST + dnt * 16 + vb_coff));
                mma16816(of[2 * dnt],     a, bb[0], bb[1]);
                mma16816(of[2 * dnt + 1], a, bb[2], bb[3]);
            }
        }
        __syncthreads();
    }

    // ---- epilogue: O / l ----
    float l0 = lacc[0], l1 = lacc[2];
    float rl0 = (l0 > 0.0f) ? __fdividef(1.0f, l0) : 0.0f;
    float rl1 = (l1 > 0.0f) ? __fdividef(1.0f, l1) : 0.0f;
    __half* orow0 = g_oh + (size_t)(b * SQ_ + q0 + m0 + gid) * EDIM + h * HD_;
    __half* orow1 = orow0 + (size_t)8 * EDIM;
#pragma unroll
    for (int nt = 0; nt < 16; nt++) {
        int c = nt * 8 + tig * 2;
        *(__half2*)(orow0 + c) = __floats2half2_rn(of[nt][0] * rl0, of[nt][1] * rl0);
        *(__half2*)(orow1 + c) = __floats2half2_rn(of[nt][2] * rl1, of[nt][3] * rl1);
    }
}

// ---------------------------------------------------------------------------
extern "C" void kernel_launch(void* const* d_in, const int* in_sizes, int n_in,
                              void* d_out, int out_size)
{
    (void)in_sizes; (void)n_in; (void)out_size;
    const float* query = (const float*)d_in[0];
    const float* key   = (const float*)d_in[1];
    const float* value = (const float*)d_in[2];
    const int*   amask = (const int*)d_in[3];
    const float* Wq    = (const float*)d_in[4];
    const float* bq    = (const float*)d_in[5];
    const float* Wk    = (const float*)d_in[6];
    const float* bk    = (const float*)d_in[7];
    const float* Wv    = (const float*)d_in[8];
    const float* bv    = (const float*)d_in[9];
    const float* Wo    = (const float*)d_in[10];
    const float* bo    = (const float*)d_in[11];
    float* out = (float*)d_out;

    const int attn_smem = 384 * SST * (int)sizeof(__half);           // 104448
    const int gemm_smem = 3 * G_STAGE * (int)sizeof(__half);         // 110592
    cudaFuncSetAttribute(attn_kernel, cudaFuncAttributeMaxDynamicSharedMemorySize, attn_smem);
    cudaFuncSetAttribute(gemm_qkv_kernel, cudaFuncAttributeMaxDynamicSharedMemorySize, gemm_smem);
    cudaFuncSetAttribute(gemm_out_kernel, cudaFuncAttributeMaxDynamicSharedMemorySize, gemm_smem);

    // fused converts (32 elts/thread, MLP=8) + mask packing (one launch)
    prep_kernel<<<6656, 256>>>(query, key, value, Wq, Wk, Wv, Wo, amask);

    // merged Q/K/V projections
    gemm_qkv_kernel<<<dim3(16, 64, 3), 256, gemm_smem>>>(bq, bk, bv);

    // attention
    dim3 gattn(SQ_ / 128, B_ * H_);              // (8, 128)
    attn_kernel<<<gattn, dim3(256), attn_smem>>>();

    // output projection
    gemm_out_kernel<<<dim3(16, 64), 256, gemm_smem>>>(bo, out);
}

// round 16
// speedup vs baseline: 1.0090x; 1.0090x over previous
#include <cuda_runtime.h>
#include <cuda_fp16.h>

#define B_    8
#define SQ_   1024
#define SK_   1024
#define QDIM  2048
#define KVDIM 1024
#define EDIM  2048
#define H_    16
#define HD_   128

// Scratch (allocation-free: __device__ globals)
__device__ __half g_qh[(size_t)B_ * H_ * SQ_ * HD_];   // [B,H,SQ,HD] fp16 (scaled by HD^-0.5*log2e)
__device__ __half g_kh[(size_t)B_ * H_ * SK_ * HD_];
__device__ __half g_vh[(size_t)B_ * H_ * SK_ * HD_];
__device__ __half g_oh[(size_t)B_ * SQ_ * EDIM];       // attention out, fp16 [B,SQ,E]
__device__ __half g_x16[33554432];                     // fp16 query|key|value
__device__ __half g_w16[12582912];                     // fp16 Wq|Wk|Wv|Wo
__device__ unsigned g_mpack[(size_t)B_ * SQ_ * (SK_ / 32)];  // packed mask bits (1MB)

// ---------------------------------------------------------------------------
// PTX helpers
// ---------------------------------------------------------------------------
__device__ __forceinline__ unsigned smem_u32(const void* p) {
    return (unsigned)__cvta_generic_to_shared(p);
}
__device__ __forceinline__ void ldm_x4(unsigned* r, unsigned addr) {
    asm volatile("ldmatrix.sync.aligned.m8n8.x4.shared.b16 {%0,%1,%2,%3}, [%4];"
                 : "=r"(r[0]), "=r"(r[1]), "=r"(r[2]), "=r"(r[3]) : "r"(addr));
}
__device__ __forceinline__ void ldm_x4_t(unsigned* r, unsigned addr) {
    asm volatile("ldmatrix.sync.aligned.m8n8.x4.trans.shared.b16 {%0,%1,%2,%3}, [%4];"
                 : "=r"(r[0]), "=r"(r[1]), "=r"(r[2]), "=r"(r[3]) : "r"(addr));
}
__device__ __forceinline__ void mma16816(float* d, const unsigned* a, unsigned b0, unsigned b1) {
    asm volatile("mma.sync.aligned.m16n8k16.row.col.f32.f16.f16.f32 "
                 "{%0,%1,%2,%3}, {%4,%5,%6,%7}, {%8,%9}, {%0,%1,%2,%3};"
                 : "+f"(d[0]), "+f"(d[1]), "+f"(d[2]), "+f"(d[3])
                 : "r"(a[0]), "r"(a[1]), "r"(a[2]), "r"(a[3]), "r"(b0), "r"(b1));
}
__device__ __forceinline__ void cp16(unsigned saddr, const void* g) {
    asm volatile("cp.async.cg.shared.global [%0], [%1], 16;" :: "r"(saddr), "l"(g) : "memory");
}
__device__ __forceinline__ void cp_commit() {
    asm volatile("cp.async.commit_group;" ::: "memory");
}
template <int N>
__device__ __forceinline__ void cp_wait() {
    asm volatile("cp.async.wait_group %0;" :: "n"(N) : "memory");
}
__device__ __forceinline__ unsigned pack_h2(float a, float b) {
    __half2 h = __floats2half2_rn(a, b);
    return *reinterpret_cast<unsigned*>(&h);
}
__device__ __forceinline__ unsigned ex2_h2(unsigned x) {
    unsigned r;
    asm("ex2.approx.f16x2 %0, %1;" : "=r"(r) : "r"(x));
    return r;
}

// ---------------------------------------------------------------------------
// Fused prep (R14 verified): fp32->fp16 converts (16 elts/thread) + mask
// bit-packing.
// ---------------------------------------------------------------------------
__global__ void __launch_bounds__(256)
prep_kernel(const float* __restrict__ q, const float* __restrict__ k,
            const float* __restrict__ v, const float* __restrict__ wq,
            const float* __restrict__ wk, const float* __restrict__ wv,
            const float* __restrict__ wo, const int* __restrict__ mask)
{
    int blk = blockIdx.x;
    if (blk >= 11264) {
        int warp = ((blk - 11264) << 3) + (threadIdx.x >> 5);   // row 0..8191
        int lane = threadIdx.x & 31;
        const int* rowp = mask + (size_t)warp * SK_;
        unsigned* op = g_mpack + (size_t)warp * (SK_ / 32);
#pragma unroll
        for (int w = 0; w < SK_ / 32; w++) {
            int mv = rowp[w * 32 + lane];
            unsigned word = __ballot_sync(0xffffffffu, mv != 0);
            if (lane == 0) op[w] = word;
        }
        return;
    }
    const float* src;
    __half* dst;
    int rel;
    if (blk < 4096)        { src = q;  dst = g_x16;            rel = blk; }
    else if (blk < 6144)   { src = k;  dst = g_x16 + 16777216; rel = blk - 4096; }
    else if (blk < 8192)   { src = v;  dst = g_x16 + 25165824; rel = blk - 6144; }
    else if (blk < 9216)   { src = wq; dst = g_w16;            rel = blk - 8192; }
    else if (blk < 9728)   { src = wk; dst = g_w16 + 4194304;  rel = blk - 9216; }
    else if (blk < 10240)  { src = wv; dst = g_w16 + 6291456;  rel = blk - 9728; }
    else                   { src = wo; dst = g_w16 + 8388608;  rel = blk - 10240; }

    int i = (rel * 256 + threadIdx.x) * 16;
    float4 f0 = *(const float4*)(src + i);
    float4 f1 = *(const float4*)(src + i + 4);
    float4 f2 = *(const float4*)(src + i + 8);
    float4 f3 = *(const float4*)(src + i + 12);
    __half2 h0[4], h1[4];
    h0[0] = __floats2half2_rn(f0.x, f0.y);
    h0[1] = __floats2half2_rn(f0.z, f0.w);
    h0[2] = __floats2half2_rn(f1.x, f1.y);
    h0[3] = __floats2half2_rn(f1.z, f1.w);
    h1[0] = __floats2half2_rn(f2.x, f2.y);
    h1[1] = __floats2half2_rn(f2.z, f2.w);
    h1[2] = __floats2half2_rn(f3.x, f3.y);
    h1[3] = __floats2half2_rn(f3.z, f3.w);
    *(int4*)(dst + i)     = *(int4*)h0;
    *(int4*)(dst + i + 8) = *(int4*)h1;
}

// ---------------------------------------------------------------------------
// GEMM body (round-9/11 verified config). C = A @ W^T + bias, *scale.
// 128x128 block, 256 threads, 8 warps (4Mx2N), warp 32x64, BK=64, 3-stage.
// MODE 0: fp32 row-major out (write-through). MODE 1: fp16 head-split out.
// ---------------------------------------------------------------------------
#define G_LDS   72
#define G_STAGE (256 * G_LDS)

template <int MODE>
__device__ __forceinline__ void
gemm_body(const __half* __restrict__ A, const __half* __restrict__ W,
          const float* __restrict__ bias, int N, int K,
          float out_scale, float* __restrict__ outF, __half* __restrict__ outH,
          __half* smem)
{
    constexpr int BK = 64, S = 3;

    const int tid  = threadIdx.x;
    const int wid  = tid >> 5;
    const int lane = tid & 31;
    const int warpM = wid >> 1;
    const int warpN = wid & 1;
    const int bm0 = blockIdx.y * 128;
    const int bn0 = blockIdx.x * 128;
    const int T = K / BK;

    const int cp_row = tid >> 3;
    const int cp_c8  = (tid & 7) * 8;

    auto copy_tile = [&](int t, int s) {
        __half* sA = smem + s * G_STAGE;
        __half* sB = sA + 128 * G_LDS;
        const __half* ga = A + (size_t)bm0 * K + t * BK;
        const __half* gw = W + (size_t)bn0 * K + t * BK;
#pragma unroll
        for (int it = 0; it < 4; it++) {
            int row = it * 32 + cp_row;
            cp16(smem_u32(sA + row * G_LDS + cp_c8), ga + (size_t)row * K + cp_c8);
            cp16(smem_u32(sB + row * G_LDS + cp_c8), gw + (size_t)row * K + cp_c8);
        }
    };

    float acc[2][8][4];
#pragma unroll
    for (int i = 0; i < 2; i++)
#pragma unroll
        for (int j = 0; j < 8; j++)
#pragma unroll
            for (int c = 0; c < 4; c++) acc[i][j][c] = 0.0f;

    const int a_row = warpM * 32 + (lane & 15);
    const int a_co  = (lane >> 4) * 8;
    const int b_row = warpN * 64 + (lane & 15);
    const int b_co  = ((lane >> 4) & 1) * 8;

    copy_tile(0, 0); cp_commit();
    copy_tile(1, 1); cp_commit();

    for (int t = 0; t < T; t++) {
        cp_wait<S - 2>();
        __syncthreads();
        if (t + S - 1 < T) copy_tile(t + S - 1, (t + S - 1) % S);
        cp_commit();

        const __half* sA = smem + (t % S) * G_STAGE;
        const __half* sB = sA + 128 * G_LDS;
#pragma unroll
        for (int kt = 0; kt < 4; kt++) {
            unsigned a0[4], a1[4];
            ldm_x4(a0, smem_u32(sA + (a_row)      * G_LDS + kt * 16 + a_co));
            ldm_x4(a1, smem_u32(sA + (a_row + 16) * G_LDS + kt * 16 + a_co));
#pragma unroll
            for (int nj = 0; nj < 4; nj++) {
                unsigned bb[4];
                ldm_x4(bb, smem_u32(sB + (b_row + nj * 16) * G_LDS + kt * 16 + b_co));
                mma16816(acc[0][2 * nj],     a0, bb[0], bb[2]);
                mma16816(acc[0][2 * nj + 1], a0, bb[1], bb[3]);
                mma16816(acc[1][2 * nj],     a1, bb[0], bb[2]);
                mma16816(acc[1][2 * nj + 1], a1, bb[1], bb[3]);
            }
        }
    }

    const int gid = lane >> 2;
    const int tig = lane & 3;

    // Hoisted bias loads (n depends only on nj)
    float2 bv8[8];
#pragma unroll
    for (int nj = 0; nj < 8; nj++)
        bv8[nj] = *(const float2*)(bias + bn0 + warpN * 64 + nj * 8 + tig * 2);

#pragma unroll
    for (int mi = 0; mi < 2; mi++) {
        int m = bm0 + warpM * 32 + mi * 16 + gid;
#pragma unroll
        for (int nj = 0; nj < 8; nj++) {
            int n = bn0 + warpN * 64 + nj * 8 + tig * 2;
            float2 bv = bv8[nj];
            float v0 = (acc[mi][nj][0] + bv.x) * out_scale;
            float v1 = (acc[mi][nj][1] + bv.y) * out_scale;
            float v2 = (acc[mi][nj][2] + bv.x) * out_scale;
            float v3 = (acc[mi][nj][3] + bv.y) * out_scale;
            if (MODE == 0) {
                float2 w0 = {v0, v1}, w1 = {v2, v3};
                __stwt((float2*)(outF + (size_t)m * N + n), w0);
                __stwt((float2*)(outF + (size_t)(m + 8) * N + n), w1);
            } else {
                int b = m >> 10, s = m & 1023;
                int h = n >> 7,  d = n & 127;
                __half* p = outH + (((size_t)b * H_ + h) * SQ_ + s) * HD_ + d;
                *(__half2*)p = __floats2half2_rn(v0, v1);
                *(__half2*)(p + 8 * HD_) = __floats2half2_rn(v2, v3);
            }
        }
    }
}

// Merged Q/K/V projection launch: blockIdx.z selects the GEMM.
__global__ void __launch_bounds__(256, 2)
gemm_qkv_kernel(const float* __restrict__ bq, const float* __restrict__ bk,
                const float* __restrict__ bv)
{
    extern __shared__ __half smem[];
    const float qscale = 0.12751879526654466f;   // HD^-0.5 * log2(e)
    int z = blockIdx.z;
    if (z == 0) {
        gemm_body<1>(g_x16, g_w16, bq, EDIM, QDIM, qscale, nullptr, g_qh, smem);
    } else if (z == 1) {
        gemm_body<1>(g_x16 + 16777216, g_w16 + 4194304, bk, EDIM, KVDIM, 1.0f, nullptr, g_kh, smem);
    } else {
        gemm_body<1>(g_x16 + 25165824, g_w16 + 6291456, bv, EDIM, KVDIM, 1.0f, nullptr, g_vh, smem);
    }
}

// Output projection: C = g_oh @ Wo^T + bo -> fp32 d_out.
__global__ void __launch_bounds__(256, 2)
gemm_out_kernel(const float* __restrict__ bo, float* __restrict__ out)
{
    extern __shared__ __half smem[];
    gemm_body<0>(g_oh, g_w16 + 8388608, bo, EDIM, EDIM, 1.0f, out, nullptr, smem);
}

// ---------------------------------------------------------------------------
// Single-pass FlashAttention, fixed-shift log2-domain softmax (verified R8)
// + hoisted mask fast path (verified R14). SST=136, 2-buffer KV, 2 CTAs/SM.
// New: Q tile loaded via cp.async in the same group as KV tile 0; mask-hoist
// LDGs issued first so their latency overlaps the copy issue window.
// ---------------------------------------------------------------------------
#define SST 136
#define ONES_H2 0x3C003C00u

__global__ void __launch_bounds__(256, 2)
attn_kernel()
{
    extern __shared__ __half sm[];
    __half* Qs = sm;

    const int tid  = threadIdx.x;
    const int warp = tid >> 5;
    const int lane = tid & 31;
    const int gid  = lane >> 2;
    const int tig  = lane & 3;
    const int q0   = blockIdx.x * 128;
    const int bh   = blockIdx.y;
    const int b    = bh >> 4;
    const int h    = bh & 15;
    const int m0   = warp * 16;

    // Issue mask-hoist loads FIRST (long-latency LDGs overlap the copies below)
    const unsigned* mp0 = g_mpack + (size_t)(b * SQ_ + q0 + m0 + gid) * (SK_ / 32);
    const unsigned* mp1 = mp0 + 8 * (SK_ / 32);
    uint4 mw[8];
#pragma unroll
    for (int w4 = 0; w4 < 4; w4++) {
        mw[2 * w4]     = *(const uint4*)(mp0 + w4 * 8);
        mw[2 * w4 + 1] = *(const uint4*)(mp0 + w4 * 8 + 4);
    }
    uint4 mw1[8];
#pragma unroll
    for (int w4 = 0; w4 < 4; w4++) {
        mw1[2 * w4]     = *(const uint4*)(mp1 + w4 * 8);
        mw1[2 * w4 + 1] = *(const uint4*)(mp1 + w4 * 8 + 4);
    }

    const __half* kroot = g_kh + (size_t)bh * SK_ * HD_;
    const __half* vroot = g_vh + (size_t)bh * SK_ * HD_;

    auto copy_tile = [&](int j, int buf) {
        const __half* kb = kroot + (size_t)j * 64 * HD_;
        const __half* vb = vroot + (size_t)j * 64 * HD_;
        __half* ks = sm + (128 + 128 * buf) * SST;
        __half* vs = ks + 64 * SST;
#pragma unroll
        for (int it = 0; it < 4; it++) {
            int slot = it * 256 + tid;
            int r = slot >> 4, c8 = slot & 15;
            cp16(smem_u32(ks + r * SST + c8 * 8), kb + r * HD_ + c8 * 8);
            cp16(smem_u32(vs + r * SST + c8 * 8), vb + r * HD_ + c8 * 8);
        }
    };

    // Q tile (128x128) via cp.async, grouped with KV tile 0
    const __half* qbase = g_qh + ((size_t)bh * SQ_ + q0) * HD_;
#pragma unroll
    for (int it = 0; it < 8; it++) {
        int slot = it * 256 + tid;
        int r = slot >> 4, c8 = slot & 15;
        cp16(smem_u32(Qs + r * SST + c8 * 8), qbase + r * HD_ + c8 * 8);
    }
    copy_tile(0, 0);
    cp_commit();

    // Finish mask hoist (registers already in flight)
    unsigned allw = ~0u;
#pragma unroll
    for (int w4 = 0; w4 < 8; w4++) {
        allw &= mw[w4].x & mw[w4].y & mw[w4].z & mw[w4].w;
        allw &= mw1[w4].x & mw1[w4].y & mw1[w4].z & mw1[w4].w;
    }
    const bool rows_unmasked = (allw == ~0u);

    float of[16][4];
#pragma unroll
    for (int i = 0; i < 16; i++)
#pragma unroll
        for (int j = 0; j < 4; j++) of[i][j] = 0.0f;
    float lacc[4] = {0.0f, 0.0f, 0.0f, 0.0f};   // ones-MMA row sums

    const unsigned q_row = m0 + (lane & 15);
    const unsigned q_coff = (lane >> 4) * 8;
    const unsigned kb_row = lane & 15;
    const unsigned kb_coff = ((lane >> 4) & 1) * 8;
    const unsigned vb_coff = (lane >> 4) * 8;

    for (int j = 0; j < 16; j++) {
        const int buf = j & 1;
        if (j < 15) {
            copy_tile(j + 1, buf ^ 1);
            cp_commit();
            cp_wait<1>();
        } else {
            cp_wait<0>();
        }
        __syncthreads();

        __half* ks = sm + (128 + 128 * buf) * SST;
        __half* vs = ks + 64 * SST;

        // ---- S = Q @ K^T (log2-domain scores) ----
        float sfr[8][4];
#pragma unroll
        for (int nt = 0; nt < 8; nt++)
#pragma unroll
            for (int c = 0; c < 4; c++) sfr[nt][c] = 0.0f;

#pragma unroll
        for (int kt = 0; kt < 8; kt++) {
            unsigned a[4];
            ldm_x4(a, smem_u32(Qs + q_row * SST + kt * 16 + q_coff));
#pragma unroll
            for (int dnt = 0; dnt < 4; dnt++) {
                unsigned bb[4];
                ldm_x4(bb, smem_u32(ks + (dnt * 16 + kb_row) * SST + kt * 16 + kb_coff));
                mma16816(sfr[2 * dnt],     a, bb[0], bb[2]);
                mma16816(sfr[2 * dnt + 1], a, bb[1], bb[3]);
            }
        }

        // ---- P = 2^S via ex2.f16x2 (hoisted fast path) ----
        unsigned ph[8][2];
        if (rows_unmasked) {
#pragma unroll
            for (int nt = 0; nt < 8; nt++) {
                ph[nt][0] = ex2_h2(pack_h2(sfr[nt][0], sfr[nt][1]));
                ph[nt][1] = ex2_h2(pack_h2(sfr[nt][2], sfr[nt][3]));
            }
        } else {
            uint2 w0 = *(const uint2*)(mp0 + j * 2);
            uint2 w1 = *(const uint2*)(mp1 + j * 2);
            unsigned long long M0 = (unsigned long long)w0.x | ((unsigned long long)w0.y << 32);
            unsigned long long M1 = (unsigned long long)w1.x | ((unsigned long long)w1.y << 32);
#pragma unroll
            for (int nt = 0; nt < 8; nt++) {
                int sh = nt * 8 + tig * 2;
                float s0 = ((M0 >> sh) & 1)       ? sfr[nt][0] : -30000.0f;
                float s1 = ((M0 >> (sh + 1)) & 1) ? sfr[nt][1] : -30000.0f;
                float s2 = ((M1 >> sh) & 1)       ? sfr[nt][2] : -30000.0f;
                float s3 = ((M1 >> (sh + 1)) & 1) ? sfr[nt][3] : -30000.0f;
                ph[nt][0] = ex2_h2(pack_h2(s0, s1));
                ph[nt][1] = ex2_h2(pack_h2(s2, s3));
            }
        }

        // ---- O += P @ V;  l += P @ ones ----
#pragma unroll
        for (int kt = 0; kt < 4; kt++) {
            unsigned a[4] = { ph[2 * kt][0], ph[2 * kt][1], ph[2 * kt + 1][0], ph[2 * kt + 1][1] };
            mma16816(lacc, a, ONES_H2, ONES_H2);
#pragma unroll
            for (int dnt = 0; dnt < 8; dnt++) {
                unsigned bb[4];
                ldm_x4_t(bb, smem_u32(vs + (kt * 16 + kb_row) * SST + dnt * 16 + vb_coff));
                mma16816(of[2 * dnt],     a, bb[0], bb[1]);
                mma16816(of[2 * dnt + 1], a, bb[2], bb[3]);
            }
        }
        __syncthreads();
    }

    // ---- epilogue: O / l ----
    float l0 = lacc[0], l1 = lacc[2];
    float rl0 = (l0 > 0.0f) ? __fdividef(1.0f, l0) : 0.0f;
    float rl1 = (l1 > 0.0f) ? __fdividef(1.0f, l1) : 0.0f;
    __half* orow0 = g_oh + (size_t)(b * SQ_ + q0 + m0 + gid) * EDIM + h * HD_;
    __half* orow1 = orow0 + (size_t)8 * EDIM;
#pragma unroll
    for (int nt = 0; nt < 16; nt++) {
        int c = nt * 8 + tig * 2;
        *(__half2*)(orow0 + c) = __floats2half2_rn(of[nt][0] * rl0, of[nt][1] * rl0);
        *(__half2*)(orow1 + c) = __floats2half2_rn(of[nt][2] * rl1, of[nt][3] * rl1);
    }
}

// ---------------------------------------------------------------------------
extern "C" void kernel_launch(void* const* d_in, const int* in_sizes, int n_in,
                              void* d_out, int out_size)
{
    (void)in_sizes; (void)n_in; (void)out_size;
    const float* query = (const float*)d_in[0];
    const float* key   = (const float*)d_in[1];
    const float* value = (const float*)d_in[2];
    const int*   amask = (const int*)d_in[3];
    const float* Wq    = (const float*)d_in[4];
    const float* bq    = (const float*)d_in[5];
    const float* Wk    = (const float*)d_in[6];
    const float* bk    = (const float*)d_in[7];
    const float* Wv    = (const float*)d_in[8];
    const float* bv    = (const float*)d_in[9];
    const float* Wo    = (const float*)d_in[10];
    const float* bo    = (const float*)d_in[11];
    float* out = (float*)d_out;

    const int attn_smem = 384 * SST * (int)sizeof(__half);           // 104448
    const int gemm_smem = 3 * G_STAGE * (int)sizeof(__half);         // 110592
    cudaFuncSetAttribute(attn_kernel, cudaFuncAttributeMaxDynamicSharedMemorySize, attn_smem);
    cudaFuncSetAttribute(gemm_qkv_kernel, cudaFuncAttributeMaxDynamicSharedMemorySize, gemm_smem);
    cudaFuncSetAttribute(gemm_out_kernel, cudaFuncAttributeMaxDynamicSharedMemorySize, gemm_smem);

    // fused converts (16 elts/thread, R14 verified) + mask packing
    prep_kernel<<<12288, 256>>>(query, key, value, Wq, Wk, Wv, Wo, amask);

    // merged Q/K/V projections
    gemm_qkv_kernel<<<dim3(16, 64, 3), 256, gemm_smem>>>(bq, bk, bv);

    // attention
    dim3 gattn(SQ_ / 128, B_ * H_);              // (8, 128)
    attn_kernel<<<gattn, dim3(256), attn_smem>>>();

    // output projection
    gemm_out_kernel<<<dim3(16, 64), 256, gemm_smem>>>(bo, out);
}

// round 17
// speedup vs baseline: 1.0155x; 1.0065x over previous
#include <cuda_runtime.h>
#include <cuda_fp16.h>

#define B_    8
#define SQ_   1024
#define SK_   1024
#define QDIM  2048
#define KVDIM 1024
#define EDIM  2048
#define H_    16
#define HD_   128

// Scratch (allocation-free: __device__ globals)
__device__ __half g_qh[(size_t)B_ * H_ * SQ_ * HD_];   // [B,H,SQ,HD] fp16 (scaled by HD^-0.5*log2e)
__device__ __half g_kh[(size_t)B_ * H_ * SK_ * HD_];
__device__ __half g_vh[(size_t)B_ * H_ * SK_ * HD_];
__device__ __half g_oh[(size_t)B_ * SQ_ * EDIM];       // attention out, fp16 [B,SQ,E]
__device__ __half g_x16[33554432];                     // fp16 query|key|value
__device__ __half g_w16[12582912];                     // fp16 Wq|Wk|Wv|Wo
__device__ unsigned g_mpack[(size_t)B_ * SQ_ * (SK_ / 32)];  // packed mask bits (1MB)

// ---------------------------------------------------------------------------
// PTX helpers
// ---------------------------------------------------------------------------
__device__ __forceinline__ unsigned smem_u32(const void* p) {
    return (unsigned)__cvta_generic_to_shared(p);
}
__device__ __forceinline__ void ldm_x4(unsigned* r, unsigned addr) {
    asm volatile("ldmatrix.sync.aligned.m8n8.x4.shared.b16 {%0,%1,%2,%3}, [%4];"
                 : "=r"(r[0]), "=r"(r[1]), "=r"(r[2]), "=r"(r[3]) : "r"(addr));
}
__device__ __forceinline__ void ldm_x4_t(unsigned* r, unsigned addr) {
    asm volatile("ldmatrix.sync.aligned.m8n8.x4.trans.shared.b16 {%0,%1,%2,%3}, [%4];"
                 : "=r"(r[0]), "=r"(r[1]), "=r"(r[2]), "=r"(r[3]) : "r"(addr));
}
__device__ __forceinline__ void mma16816(float* d, const unsigned* a, unsigned b0, unsigned b1) {
    asm volatile("mma.sync.aligned.m16n8k16.row.col.f32.f16.f16.f32 "
                 "{%0,%1,%2,%3}, {%4,%5,%6,%7}, {%8,%9}, {%0,%1,%2,%3};"
                 : "+f"(d[0]), "+f"(d[1]), "+f"(d[2]), "+f"(d[3])
                 : "r"(a[0]), "r"(a[1]), "r"(a[2]), "r"(a[3]), "r"(b0), "r"(b1));
}
__device__ __forceinline__ void cp16(unsigned saddr, const void* g) {
    asm volatile("cp.async.cg.shared.global [%0], [%1], 16;" :: "r"(saddr), "l"(g) : "memory");
}
__device__ __forceinline__ void cp_commit() {
    asm volatile("cp.async.commit_group;" ::: "memory");
}
template <int N>
__device__ __forceinline__ void cp_wait() {
    asm volatile("cp.async.wait_group %0;" :: "n"(N) : "memory");
}
__device__ __forceinline__ unsigned pack_h2(float a, float b) {
    __half2 h = __floats2half2_rn(a, b);
    return *reinterpret_cast<unsigned*>(&h);
}
__device__ __forceinline__ unsigned ex2_h2(unsigned x) {
    unsigned r;
    asm("ex2.approx.f16x2 %0, %1;" : "=r"(r) : "r"(x));
    return r;
}

// ---------------------------------------------------------------------------
// Fused prep: fp32->fp16 converts (16 elts/thread) + mask bit-packing.
// ---------------------------------------------------------------------------
__global__ void __launch_bounds__(256)
prep_kernel(const float* __restrict__ q, const float* __restrict__ k,
            const float* __restrict__ v, const float* __restrict__ wq,
            const float* __restrict__ wk, const float* __restrict__ wv,
            const float* __restrict__ wo, const int* __restrict__ mask)
{
    int blk = blockIdx.x;
    if (blk >= 11264) {
        int warp = ((blk - 11264) << 3) + (threadIdx.x >> 5);   // row 0..8191
        int lane = threadIdx.x & 31;
        const int* rowp = mask + (size_t)warp * SK_;
        unsigned* op = g_mpack + (size_t)warp * (SK_ / 32);
#pragma unroll
        for (int w = 0; w < SK_ / 32; w++) {
            int mv = rowp[w * 32 + lane];
            unsigned word = __ballot_sync(0xffffffffu, mv != 0);
            if (lane == 0) op[w] = word;
        }
        return;
    }
    const float* src;
    __half* dst;
    int rel;
    if (blk < 4096)        { src = q;  dst = g_x16;            rel = blk; }
    else if (blk < 6144)   { src = k;  dst = g_x16 + 16777216; rel = blk - 4096; }
    else if (blk < 8192)   { src = v;  dst = g_x16 + 25165824; rel = blk - 6144; }
    else if (blk < 9216)   { src = wq; dst = g_w16;            rel = blk - 8192; }
    else if (blk < 9728)   { src = wk; dst = g_w16 + 4194304;  rel = blk - 9216; }
    else if (blk < 10240)  { src = wv; dst = g_w16 + 6291456;  rel = blk - 9728; }
    else                   { src = wo; dst = g_w16 + 8388608;  rel = blk - 10240; }

    int i = (rel * 256 + threadIdx.x) * 16;
    float4 f0 = *(const float4*)(src + i);
    float4 f1 = *(const float4*)(src + i + 4);
    float4 f2 = *(const float4*)(src + i + 8);
    float4 f3 = *(const float4*)(src + i + 12);
    __half2 h0[4], h1[4];
    h0[0] = __floats2half2_rn(f0.x, f0.y);
    h0[1] = __floats2half2_rn(f0.z, f0.w);
    h0[2] = __floats2half2_rn(f1.x, f1.y);
    h0[3] = __floats2half2_rn(f1.z, f1.w);
    h1[0] = __floats2half2_rn(f2.x, f2.y);
    h1[1] = __floats2half2_rn(f2.z, f2.w);
    h1[2] = __floats2half2_rn(f3.x, f3.y);
    h1[3] = __floats2half2_rn(f3.z, f3.w);
    *(int4*)(dst + i)     = *(int4*)h0;
    *(int4*)(dst + i + 8) = *(int4*)h1;
}

// ---------------------------------------------------------------------------
// GEMM body (round-9/11 verified config). C = A @ W^T + bias, *scale.
// 128x128 block, 256 threads, 8 warps (4Mx2N), warp 32x64, BK=64, 3-stage.
// MODE 0: fp32 row-major out (write-through, never re-read).
// MODE 1: fp16 head-split out.
// ---------------------------------------------------------------------------
#define G_LDS   72
#define G_STAGE (256 * G_LDS)

template <int MODE>
__device__ __forceinline__ void
gemm_body(const __half* __restrict__ A, const __half* __restrict__ W,
          const float* __restrict__ bias, int N, int K,
          float out_scale, float* __restrict__ outF, __half* __restrict__ outH,
          __half* smem)
{
    constexpr int BK = 64, S = 3;

    const int tid  = threadIdx.x;
    const int wid  = tid >> 5;
    const int lane = tid & 31;
    const int warpM = wid >> 1;
    const int warpN = wid & 1;
    const int bm0 = blockIdx.y * 128;
    const int bn0 = blockIdx.x * 128;
    const int T = K / BK;

    const int cp_row = tid >> 3;
    const int cp_c8  = (tid & 7) * 8;

    auto copy_tile = [&](int t, int s) {
        __half* sA = smem + s * G_STAGE;
        __half* sB = sA + 128 * G_LDS;
        const __half* ga = A + (size_t)bm0 * K + t * BK;
        const __half* gw = W + (size_t)bn0 * K + t * BK;
#pragma unroll
        for (int it = 0; it < 4; it++) {
            int row = it * 32 + cp_row;
            cp16(smem_u32(sA + row * G_LDS + cp_c8), ga + (size_t)row * K + cp_c8);
            cp16(smem_u32(sB + row * G_LDS + cp_c8), gw + (size_t)row * K + cp_c8);
        }
    };

    float acc[2][8][4];
#pragma unroll
    for (int i = 0; i < 2; i++)
#pragma unroll
        for (int j = 0; j < 8; j++)
#pragma unroll
            for (int c = 0; c < 4; c++) acc[i][j][c] = 0.0f;

    const int a_row = warpM * 32 + (lane & 15);
    const int a_co  = (lane >> 4) * 8;
    const int b_row = warpN * 64 + (lane & 15);
    const int b_co  = ((lane >> 4) & 1) * 8;

    copy_tile(0, 0); cp_commit();
    copy_tile(1, 1); cp_commit();

    for (int t = 0; t < T; t++) {
        cp_wait<S - 2>();
        __syncthreads();
        if (t + S - 1 < T) copy_tile(t + S - 1, (t + S - 1) % S);
        cp_commit();

        const __half* sA = smem + (t % S) * G_STAGE;
        const __half* sB = sA + 128 * G_LDS;
#pragma unroll
        for (int kt = 0; kt < 4; kt++) {
            unsigned a0[4], a1[4];
            ldm_x4(a0, smem_u32(sA + (a_row)      * G_LDS + kt * 16 + a_co));
            ldm_x4(a1, smem_u32(sA + (a_row + 16) * G_LDS + kt * 16 + a_co));
#pragma unroll
            for (int nj = 0; nj < 4; nj++) {
                unsigned bb[4];
                ldm_x4(bb, smem_u32(sB + (b_row + nj * 16) * G_LDS + kt * 16 + b_co));
                mma16816(acc[0][2 * nj],     a0, bb[0], bb[2]);
                mma16816(acc[0][2 * nj + 1], a0, bb[1], bb[3]);
                mma16816(acc[1][2 * nj],     a1, bb[0], bb[2]);
                mma16816(acc[1][2 * nj + 1], a1, bb[1], bb[3]);
            }
        }
    }

    const int gid = lane >> 2;
    const int tig = lane & 3;
#pragma unroll
    for (int mi = 0; mi < 2; mi++) {
        int m = bm0 + warpM * 32 + mi * 16 + gid;
#pragma unroll
        for (int nj = 0; nj < 8; nj++) {
            int n = bn0 + warpN * 64 + nj * 8 + tig * 2;
            float2 bv = *(const float2*)(bias + n);
            float v0 = (acc[mi][nj][0] + bv.x) * out_scale;
            float v1 = (acc[mi][nj][1] + bv.y) * out_scale;
            float v2 = (acc[mi][nj][2] + bv.x) * out_scale;
            float v3 = (acc[mi][nj][3] + bv.y) * out_scale;
            if (MODE == 0) {
                float2 w0 = {v0, v1}, w1 = {v2, v3};
                __stwt((float2*)(outF + (size_t)m * N + n), w0);
                __stwt((float2*)(outF + (size_t)(m + 8) * N + n), w1);
            } else {
                int b = m >> 10, s = m & 1023;
                int h = n >> 7,  d = n & 127;
                __half* p = outH + (((size_t)b * H_ + h) * SQ_ + s) * HD_ + d;
                *(__half2*)p = __floats2half2_rn(v0, v1);
                *(__half2*)(p + 8 * HD_) = __floats2half2_rn(v2, v3);
            }
        }
    }
}

// Merged Q/K/V projection launch: blockIdx.z selects the GEMM.
__global__ void __launch_bounds__(256, 2)
gemm_qkv_kernel(const float* __restrict__ bq, const float* __restrict__ bk,
                const float* __restrict__ bv)
{
    extern __shared__ __half smem[];
    const float qscale = 0.12751879526654466f;   // HD^-0.5 * log2(e)
    int z = blockIdx.z;
    if (z == 0) {
        gemm_body<1>(g_x16, g_w16, bq, EDIM, QDIM, qscale, nullptr, g_qh, smem);
    } else if (z == 1) {
        gemm_body<1>(g_x16 + 16777216, g_w16 + 4194304, bk, EDIM, KVDIM, 1.0f, nullptr, g_kh, smem);
    } else {
        gemm_body<1>(g_x16 + 25165824, g_w16 + 6291456, bv, EDIM, KVDIM, 1.0f, nullptr, g_vh, smem);
    }
}

// Output projection: C = g_oh @ Wo^T + bo -> fp32 d_out.
__global__ void __launch_bounds__(256, 2)
gemm_out_kernel(const float* __restrict__ bo, float* __restrict__ out)
{
    extern __shared__ __half smem[];
    gemm_body<0>(g_oh, g_w16 + 8388608, bo, EDIM, EDIM, 1.0f, out, nullptr, smem);
}

// ---------------------------------------------------------------------------
// Single-pass FlashAttention, fixed-shift log2-domain softmax (verified R8)
// + hoisted mask fast path: per-thread row-allones flag computed ONCE before
// the main loop; fast path has zero mask loads and zero selects per tile.
// Verified R11/R13 memory layout: SST=136, 2-buffer KV, 2 CTAs/SM.
// ---------------------------------------------------------------------------
#define SST 136
#define ONES_H2 0x3C003C00u

__global__ void __launch_bounds__(256, 2)
attn_kernel()
{
    extern __shared__ __half sm[];
    __half* Qs = sm;

    const int tid  = threadIdx.x;
    const int warp = tid >> 5;
    const int lane = tid & 31;
    const int gid  = lane >> 2;
    const int tig  = lane & 3;
    const int q0   = blockIdx.x * 128;
    const int bh   = blockIdx.y;
    const int b    = bh >> 4;
    const int h    = bh & 15;
    const int m0   = warp * 16;

    const __half* qbase = g_qh + ((size_t)bh * SQ_ + q0) * HD_;
#pragma unroll
    for (int it = 0; it < 8; it++) {
        int slot = it * 256 + tid;
        int r = slot >> 4, c8 = slot & 15;
        *(int4*)(Qs + r * SST + c8 * 8) = *(const int4*)(qbase + r * HD_ + c8 * 8);
    }

    const __half* kroot = g_kh + (size_t)bh * SK_ * HD_;
    const __half* vroot = g_vh + (size_t)bh * SK_ * HD_;

    auto copy_tile = [&](int j, int buf) {
        const __half* kb = kroot + (size_t)j * 64 * HD_;
        const __half* vb = vroot + (size_t)j * 64 * HD_;
        __half* ks = sm + (128 + 128 * buf) * SST;
        __half* vs = ks + 64 * SST;
#pragma unroll
        for (int it = 0; it < 4; it++) {
            int slot = it * 256 + tid;
            int r = slot >> 4, c8 = slot & 15;
            cp16(smem_u32(ks + r * SST + c8 * 8), kb + r * HD_ + c8 * 8);
            cp16(smem_u32(vs + r * SST + c8 * 8), vb + r * HD_ + c8 * 8);
        }
    };

    copy_tile(0, 0);
    cp_commit();

    // Hoisted mask check: are both of this thread's rows fully unmasked?
    const unsigned* mp0 = g_mpack + (size_t)(b * SQ_ + q0 + m0 + gid) * (SK_ / 32);
    const unsigned* mp1 = mp0 + 8 * (SK_ / 32);
    unsigned allw = ~0u;
#pragma unroll
    for (int w4 = 0; w4 < 8; w4++) {
        uint4 a = *(const uint4*)(mp0 + w4 * 4);
        uint4 c = *(const uint4*)(mp1 + w4 * 4);
        allw &= a.x & a.y & a.z & a.w & c.x & c.y & c.z & c.w;
    }
    const bool rows_unmasked = (allw == ~0u);

    float of[16][4];
#pragma unroll
    for (int i = 0; i < 16; i++)
#pragma unroll
        for (int j = 0; j < 4; j++) of[i][j] = 0.0f;
    float lacc[4] = {0.0f, 0.0f, 0.0f, 0.0f};   // ones-MMA row sums

    const unsigned q_row = m0 + (lane & 15);
    const unsigned q_coff = (lane >> 4) * 8;
    const unsigned kb_row = lane & 15;
    const unsigned kb_coff = ((lane >> 4) & 1) * 8;
    const unsigned vb_coff = (lane >> 4) * 8;

    for (int j = 0; j < 16; j++) {
        const int buf = j & 1;
        if (j < 15) {
            copy_tile(j + 1, buf ^ 1);
            cp_commit();
            cp_wait<1>();
        } else {
            cp_wait<0>();
        }
        __syncthreads();

        __half* ks = sm + (128 + 128 * buf) * SST;
        __half* vs = ks + 64 * SST;

        // ---- S = Q @ K^T (log2-domain scores) ----
        float sfr[8][4];
#pragma unroll
        for (int nt = 0; nt < 8; nt++)
#pragma unroll
            for (int c = 0; c < 4; c++) sfr[nt][c] = 0.0f;

#pragma unroll
        for (int kt = 0; kt < 8; kt++) {
            unsigned a[4];
            ldm_x4(a, smem_u32(Qs + q_row * SST + kt * 16 + q_coff));
#pragma unroll
            for (int dnt = 0; dnt < 4; dnt++) {
                unsigned bb[4];
                ldm_x4(bb, smem_u32(ks + (dnt * 16 + kb_row) * SST + kt * 16 + kb_coff));
                mma16816(sfr[2 * dnt],     a, bb[0], bb[2]);
                mma16816(sfr[2 * dnt + 1], a, bb[1], bb[3]);
            }
        }

        // ---- P = 2^S via ex2.f16x2 (hoisted fast path: no loads, no selects) ----
        unsigned ph[8][2];
        if (rows_unmasked) {
#pragma unroll
            for (int nt = 0; nt < 8; nt++) {
                ph[nt][0] = ex2_h2(pack_h2(sfr[nt][0], sfr[nt][1]));
                ph[nt][1] = ex2_h2(pack_h2(sfr[nt][2], sfr[nt][3]));
            }
        } else {
            uint2 w0 = *(const uint2*)(mp0 + j * 2);
            uint2 w1 = *(const uint2*)(mp1 + j * 2);
            unsigned long long M0 = (unsigned long long)w0.x | ((unsigned long long)w0.y << 32);
            unsigned long long M1 = (unsigned long long)w1.x | ((unsigned long long)w1.y << 32);
#pragma unroll
            for (int nt = 0; nt < 8; nt++) {
                int sh = nt * 8 + tig * 2;
                float s0 = ((M0 >> sh) & 1)       ? sfr[nt][0] : -30000.0f;
                float s1 = ((M0 >> (sh + 1)) & 1) ? sfr[nt][1] : -30000.0f;
                float s2 = ((M1 >> sh) & 1)       ? sfr[nt][2] : -30000.0f;
                float s3 = ((M1 >> (sh + 1)) & 1) ? sfr[nt][3] : -30000.0f;
                ph[nt][0] = ex2_h2(pack_h2(s0, s1));
                ph[nt][1] = ex2_h2(pack_h2(s2, s3));
            }
        }

        // ---- O += P @ V;  l += P @ ones ----
#pragma unroll
        for (int kt = 0; kt < 4; kt++) {
            unsigned a[4] = { ph[2 * kt][0], ph[2 * kt][1], ph[2 * kt + 1][0], ph[2 * kt + 1][1] };
            mma16816(lacc, a, ONES_H2, ONES_H2);
#pragma unroll
            for (int dnt = 0; dnt < 8; dnt++) {
                unsigned bb[4];
                ldm_x4_t(bb, smem_u32(vs + (kt * 16 + kb_row) * SST + dnt * 16 + vb_coff));
                mma16816(of[2 * dnt],     a, bb[0], bb[1]);
                mma16816(of[2 * dnt + 1], a, bb[2], bb[3]);
            }
        }
        __syncthreads();
    }

    // ---- epilogue: O / l ----
    float l0 = lacc[0], l1 = lacc[2];
    float rl0 = (l0 > 0.0f) ? __fdividef(1.0f, l0) : 0.0f;
    float rl1 = (l1 > 0.0f) ? __fdividef(1.0f, l1) : 0.0f;
    __half* orow0 = g_oh + (size_t)(b * SQ_ + q0 + m0 + gid) * EDIM + h * HD_;
    __half* orow1 = orow0 + (size_t)8 * EDIM;
#pragma unroll
    for (int nt = 0; nt < 16; nt++) {
        int c = nt * 8 + tig * 2;
        *(__half2*)(orow0 + c) = __floats2half2_rn(of[nt][0] * rl0, of[nt][1] * rl0);
        *(__half2*)(orow1 + c) = __floats2half2_rn(of[nt][2] * rl1, of[nt][3] * rl1);
    }
}

// ---------------------------------------------------------------------------
extern "C" void kernel_launch(void* const* d_in, const int* in_sizes, int n_in,
                              void* d_out, int out_size)
{
    (void)in_sizes; (void)n_in; (void)out_size;
    const float* query = (const float*)d_in[0];
    const float* key   = (const float*)d_in[1];
    const float* value = (const float*)d_in[2];
    const int*   amask = (const int*)d_in[3];
    const float* Wq    = (const float*)d_in[4];
    const float* bq    = (const float*)d_in[5];
    const float* Wk    = (const float*)d_in[6];
    const float* bk    = (const float*)d_in[7];
    const float* Wv    = (const float*)d_in[8];
    const float* bv    = (const float*)d_in[9];
    const float* Wo    = (const float*)d_in[10];
    const float* bo    = (const float*)d_in[11];
    float* out = (float*)d_out;

    const int attn_smem = 384 * SST * (int)sizeof(__half);           // 104448
    const int gemm_smem = 3 * G_STAGE * (int)sizeof(__half);         // 110592
    cudaFuncSetAttribute(attn_kernel, cudaFuncAttributeMaxDynamicSharedMemorySize, attn_smem);
    cudaFuncSetAttribute(gemm_qkv_kernel, cudaFuncAttributeMaxDynamicSharedMemorySize, gemm_smem);
    cudaFuncSetAttribute(gemm_out_kernel, cudaFuncAttributeMaxDynamicSharedMemorySize, gemm_smem);

    // fused converts (16 elts/thread) + mask packing (one launch)
    prep_kernel<<<12288, 256>>>(query, key, value, Wq, Wk, Wv, Wo, amask);

    // merged Q/K/V projections
    gemm_qkv_kernel<<<dim3(16, 64, 3), 256, gemm_smem>>>(bq, bk, bv);

    // attention
    dim3 gattn(SQ_ / 128, B_ * H_);              // (8, 128)
    attn_kernel<<<gattn, dim3(256), attn_smem>>>();

    // output projection
    gemm_out_kernel<<<dim3(16, 64), 256, gemm_smem>>>(bo, out);
}